// round 4
// baseline (speedup 1.0000x reference)
#include <cuda_runtime.h>
#include <cuda_fp16.h>
#include <math.h>
#include <stdint.h>

#define VCAB 50257
#define EDIM 256
#define HDIM 512
#define BATCH 64
#define SLEN 128
#define TLEN 64
#define TD 63            // decoder steps (T-1)
#define GDIM 2048        // 4*H
#define NB 128           // persistent grid size

// fc GEMM dims (fp16 mma.sync path)
#define KD 1024
#define MPAD 4096
#define NPAD 50432
#define NCHK 16          // KD / 64
#define STGB 32768       // stage bytes: A 16KB + B 16KB

// ---------------- scratch (static device allocations; no cudaMalloc) ----------------
__device__ __align__(16) float g_benc[GDIM];
__device__ __align__(16) float g_bdec[GDIM];
__device__ __align__(16) float g_encX[SLEN * BATCH * EDIM];
__device__ __align__(16) float g_xprojE[(size_t)SLEN * BATCH * GDIM];
__device__ __align__(16) float g_decX[TD * BATCH * EDIM];
__device__ __align__(16) float g_decxp[(size_t)TD * BATCH * GDIM];
__device__ __align__(16) float g_encout[(size_t)BATCH * SLEN * HDIM];
__device__ __align__(16) float g_encWe[(size_t)BATCH * SLEN * HDIM];
__device__ __align__(16) float g_hbuf[2][BATCH * HDIM];
__device__ __align__(16) float g_c[BATCH * HDIM];
__device__ __align__(16) float g_hwh[BATCH * HDIM];
__device__ __align__(16) float g_xcat2[2][BATCH * 1024];
__device__ __align__(16) float g_Wpack[(size_t)GDIM * 1024];
// fp16 operands for the tensor-core fc GEMM (pad rows stay zero: never written)
__device__ __align__(16) __half g_Ahf[(size_t)MPAD * KD];
__device__ __align__(16) __half g_Bhf[(size_t)NPAD * KD];

// software grid barrier state
__device__ int g_bar_cnt;
__device__ volatile unsigned g_bar_gen;

__device__ __forceinline__ float sigf(float x) { return 1.0f / (1.0f + expf(-x)); }

__device__ __forceinline__ void gridbar(unsigned& lgen) {
    __syncthreads();
    if (threadIdx.x == 0) {
        __threadfence();
        unsigned target = lgen + 1;
        if (atomicAdd(&g_bar_cnt, 1) == NB - 1) {
            atomicExch(&g_bar_cnt, 0);
            __threadfence();
            atomicExch((unsigned*)&g_bar_gen, target);
        } else {
            while (g_bar_gen != target) { __nanosleep(32); }
        }
        __threadfence();
    }
    lgen++;
    __syncthreads();
}

// load A tile [64 rows][128 k] into As[b*129 + k] (conflict-free for lane-b reads)
__device__ __forceinline__ void load_tile64(float* As, const float* src, int pitch, int k0, int tid) {
    __syncthreads();
    int b = tid & 63, kq = tid >> 6;
    const float* row = src + (size_t)b * pitch + k0 + kq * 32;
    float* drow = As + b * 129 + kq * 32;
#pragma unroll
    for (int r = 0; r < 8; r++) {
        float4 v = *(const float4*)(row + r * 4);
        drow[r * 4 + 0] = v.x; drow[r * 4 + 1] = v.y;
        drow[r * 4 + 2] = v.z; drow[r * 4 + 3] = v.w;
    }
    __syncthreads();
}

// ---------------- PTX helpers (compute_103-safe) ----------------
__device__ __forceinline__ uint32_t smem_u32(const void* p) {
    uint32_t a;
    asm("{ .reg .u64 t; cvta.to.shared.u64 t, %1; cvt.u32.u64 %0, t; }" : "=r"(a) : "l"(p));
    return a;
}
__device__ __forceinline__ void cpa16(uint32_t dst, const void* src) {
    asm volatile("cp.async.cg.shared.global [%0], [%1], 16;" :: "r"(dst), "l"(src) : "memory");
}
__device__ __forceinline__ void cpa_commit() { asm volatile("cp.async.commit_group;" ::: "memory"); }
template <int N> __device__ __forceinline__ void cpa_wait() {
    asm volatile("cp.async.wait_group %0;" :: "n"(N) : "memory");
}
#define LDMX4(r, addr) \
    asm volatile("ldmatrix.sync.aligned.m8n8.x4.shared.b16 {%0,%1,%2,%3}, [%4];" \
        : "=r"((r)[0]), "=r"((r)[1]), "=r"((r)[2]), "=r"((r)[3]) : "r"(addr))
__device__ __forceinline__ void mma16816(float* c, const uint32_t* a, uint32_t b0, uint32_t b1) {
    asm volatile("mma.sync.aligned.m16n8k16.row.col.f32.f16.f16.f32 "
        "{%0,%1,%2,%3}, {%4,%5,%6,%7}, {%8,%9}, {%0,%1,%2,%3};"
        : "+f"(c[0]), "+f"(c[1]), "+f"(c[2]), "+f"(c[3])
        : "r"(a[0]), "r"(a[1]), "r"(a[2]), "r"(a[3]), "r"(b0), "r"(b1));
}

// ---------------- setup kernels ----------------
__global__ void k_bias(const float* __restrict__ ebih, const float* __restrict__ ebhh,
                       const float* __restrict__ dbih, const float* __restrict__ dbhh) {
    int j = blockIdx.x * blockDim.x + threadIdx.x;
    if (j < GDIM) {
        g_benc[j] = ebih[j] + ebhh[j];
        g_bdec[j] = dbih[j] + dbhh[j];
    }
}

__global__ void k_wpack(const float* __restrict__ dWih, const float* __restrict__ dWhh) {
    size_t idx = (size_t)blockIdx.x * blockDim.x + threadIdx.x;
    if (idx >= (size_t)GDIM * 1024) return;
    int j = (int)(idx >> 10);
    int k = (int)(idx & 1023);
    g_Wpack[idx] = (k < HDIM) ? dWhh[(size_t)j * HDIM + k]
                              : dWih[(size_t)j * (EDIM + HDIM) + EDIM + (k - HDIM)];
}

__global__ void k_gather_enc(const float* __restrict__ emb, const int* __restrict__ src) {
    int m = blockIdx.x;
    int e = threadIdx.x;
    int s = m >> 6, b = m & 63;
    int tok = src[b * SLEN + s];
    g_encX[(size_t)m * EDIM + e] = emb[(size_t)tok * EDIM + e];
}

__global__ void k_gather_dec(const float* __restrict__ emb, const int* __restrict__ trg) {
    int m = blockIdx.x;
    int e = threadIdx.x;
    int t = m >> 6, b = m & 63;
    int tok = trg[b * TLEN + t];
    g_decX[(size_t)m * EDIM + e] = emb[(size_t)tok * EDIM + e];
}

__global__ void k_zero_out(float* __restrict__ out) {
    size_t idx = (size_t)blockIdx.x * blockDim.x + threadIdx.x;
    if (idx >= (size_t)BATCH * VCAB) return;
    size_t b = idx / VCAB, v = idx % VCAB;
    out[b * (size_t)TLEN * VCAB + v] = 0.0f;
}

__global__ void k_convB_h(const float* __restrict__ W) {
    size_t i4 = (size_t)blockIdx.x * blockDim.x + threadIdx.x;
    if (i4 * 4 >= (size_t)VCAB * KD) return;
    float4 v = *reinterpret_cast<const float4*>(W + i4 * 4);
    __half2* dst = reinterpret_cast<__half2*>(g_Bhf + i4 * 4);
    dst[0] = __floats2half2_rn(v.x, v.y);
    dst[1] = __floats2half2_rn(v.z, v.w);
}

// ---------------- persistent encoder: all 128 LSTM steps in one kernel ----------------
// Block bid owns h-dims [bid*4, bid*4+4). Thread (b = tid&63, hd = tid>>6) computes
// all 4 gates for (b, bid*4+hd) and does the cell update locally; c lives in a register.
__global__ void __launch_bounds__(256, 1) enc_persist(const float* __restrict__ Whh) {
    extern __shared__ float sdyn[];
    float* Ws = sdyn;               // [512][16]  (k, hd*4+gate)
    float* As = sdyn + 512 * 16;    // [64][129]
    const int tid = threadIdx.x, bid = blockIdx.x;
    const int b = tid & 63, hd = tid >> 6;
    const int hdabs = bid * 4 + hd;
    unsigned lgen = g_bar_gen;

    // preload the 16 Whh rows this block needs (reused for all 128 steps)
    for (int i = tid; i < 16 * 512; i += 256) {
        int k = i >> 4, c = i & 15, hh = c >> 2, gg = c & 3;
        Ws[i] = Whh[((size_t)(gg * 512 + bid * 4 + hh)) * 512 + k];
    }
    g_hbuf[0][b * 512 + hdabs] = 0.0f;
    float c_reg = 0.0f;
    gridbar(lgen);

    for (int t = 0; t < SLEN; t++) {
        const float* hcur = g_hbuf[t & 1];
        size_t xb = ((size_t)t * 64 + b) * GDIM;
        float ai = g_xprojE[xb + hdabs];
        float af = g_xprojE[xb + 512 + hdabs];
        float ag = g_xprojE[xb + 1024 + hdabs];
        float ao = g_xprojE[xb + 1536 + hdabs];
        for (int k0 = 0; k0 < 512; k0 += 128) {
            load_tile64(As, hcur, 512, k0, tid);
#pragma unroll 8
            for (int k = 0; k < 128; k++) {
                float a = As[b * 129 + k];
                float4 w = *(const float4*)&Ws[(k0 + k) * 16 + hd * 4];
                ai += a * w.x; af += a * w.y; ag += a * w.z; ao += a * w.w;
            }
        }
        float cc = sigf(af) * c_reg + sigf(ai) * tanhf(ag);
        float hh = sigf(ao) * tanhf(cc);
        c_reg = cc;
        g_encout[((size_t)b * SLEN + t) * 512 + hdabs] = hh;
        g_hbuf[(t + 1) & 1][b * 512 + hdabs] = hh;
        gridbar(lgen);
    }
    g_c[b * 512 + hdabs] = c_reg;
}

// ---------------- persistent decoder: all 63 steps, 3 phases/step ----------------
// P1: hwh = h @ Wh^T (thread (b, jq) -> hwh[b][bid*4+jq])
// P23 (blocks 0..63, b=bid): scores + softmax + context -> xcat[cur] ctx part + fp16 A
// P4: gates = xcat[cur] @ Wpack^T, cell update -> xcat[nxt] h part + fp16 A
__global__ void __launch_bounds__(256, 1) dec_persist(const float* __restrict__ attnW,
                                                      const float* __restrict__ vw) {
    extern __shared__ float sdyn[];
    float* W4 = sdyn;                    // [1024][16]
    float* W1 = W4 + 1024 * 16;          // [512][4]
    float* As = W1 + 512 * 4;            // [64][129]
    float* vws = As + 64 * 129;          // 512
    float* hwhs = vws + 512;             // 512
    float* sc = hwhs + 512;              // 128
    float* red = sc + 128;               // 128
    const int tid = threadIdx.x, bid = blockIdx.x;
    const int b = tid & 63, hd = tid >> 6;
    const int hdabs = bid * 4 + hd;
    unsigned lgen = g_bar_gen;

    for (int i = tid; i < 16 * 1024; i += 256) {
        int k = i >> 4, c = i & 15, hh = c >> 2, gg = c & 3;
        W4[i] = g_Wpack[(size_t)(gg * 512 + bid * 4 + hh) * 1024 + k];
    }
    for (int i = tid; i < 4 * 512; i += 256) {
        int k = i >> 2, jq = i & 3;
        W1[k * 4 + jq] = attnW[(size_t)(bid * 4 + jq) * (2 * HDIM) + k];
    }
    if (bid < 64)
        for (int i = tid; i < 512; i += 256) vws[i] = vw[i];

    // init: xcat[0] h-part = encoder final h; c from g_c
    g_xcat2[0][b * 1024 + hdabs] = g_hbuf[0][b * 512 + hdabs];
    float c_reg = g_c[b * 512 + hdabs];
    gridbar(lgen);

    for (int t = 0; t < TD; t++) {
        const int cur = t & 1, nxt = cur ^ 1;
        const float* xc = g_xcat2[cur];

        // ---- P1: hwh ----
        {
            float acc = 0.0f;
            for (int k0 = 0; k0 < 512; k0 += 128) {
                load_tile64(As, xc, 1024, k0, tid);
#pragma unroll 8
                for (int k = 0; k < 128; k++)
                    acc += As[b * 129 + k] * W1[(k0 + k) * 4 + hd];
            }
            g_hwh[b * 512 + bid * 4 + hd] = acc;
        }
        gridbar(lgen);

        // ---- P23: attention (blocks 0..63) ----
        if (bid < 64) {
            const int bb = bid;
            for (int i = tid; i < 512; i += 256) hwhs[i] = g_hwh[bb * 512 + i];
            __syncthreads();
            int warp = tid >> 5, lane = tid & 31;
            for (int s = warp; s < SLEN; s += 8) {
                const float* we = &g_encWe[((size_t)bb * SLEN + s) * 512];
                float a = 0.0f;
                for (int j = lane; j < 512; j += 32)
                    a += tanhf(hwhs[j] + we[j]) * vws[j];
#pragma unroll
                for (int o = 16; o > 0; o >>= 1) a += __shfl_xor_sync(0xffffffffu, a, o);
                if (lane == 0) sc[s] = a;
            }
            __syncthreads();
            if (tid < SLEN) red[tid] = sc[tid];
            __syncthreads();
            for (int o = 64; o > 0; o >>= 1) {
                if (tid < o) red[tid] = fmaxf(red[tid], red[tid + o]);
                __syncthreads();
            }
            float mx = red[0];
            __syncthreads();
            float e = 0.0f;
            if (tid < SLEN) { e = expf(sc[tid] - mx); red[tid] = e; }
            __syncthreads();
            for (int o = 64; o > 0; o >>= 1) {
                if (tid < o) red[tid] += red[tid + o];
                __syncthreads();
            }
            float inv = 1.0f / red[0];
            __syncthreads();
            if (tid < SLEN) sc[tid] = e * inv;
            __syncthreads();
            // context: thread handles cols tid and tid+256
            float c0 = 0.0f, c1 = 0.0f;
            const float* eo = &g_encout[(size_t)bb * SLEN * 512];
            for (int s = 0; s < SLEN; s++) {
                float w = sc[s];
                c0 += w * eo[s * 512 + tid];
                c1 += w * eo[s * 512 + tid + 256];
            }
            g_xcat2[cur][bb * 1024 + 512 + tid] = c0;
            g_xcat2[cur][bb * 1024 + 512 + tid + 256] = c1;
            size_t m = ((size_t)t * 64 + bb) * 1024;
            g_Ahf[m + 512 + tid] = __float2half(c0);
            g_Ahf[m + 512 + tid + 256] = __float2half(c1);
        }
        gridbar(lgen);

        // ---- P4: gates + cell ----
        {
            size_t xb = ((size_t)t * 64 + b) * GDIM;
            float ai = g_decxp[xb + hdabs];
            float af = g_decxp[xb + 512 + hdabs];
            float ag = g_decxp[xb + 1024 + hdabs];
            float ao = g_decxp[xb + 1536 + hdabs];
            for (int k0 = 0; k0 < 1024; k0 += 128) {
                load_tile64(As, xc, 1024, k0, tid);
#pragma unroll 8
                for (int k = 0; k < 128; k++) {
                    float a = As[b * 129 + k];
                    float4 w = *(const float4*)&W4[(k0 + k) * 16 + hd * 4];
                    ai += a * w.x; af += a * w.y; ag += a * w.z; ao += a * w.w;
                }
            }
            float cc = sigf(af) * c_reg + sigf(ai) * tanhf(ag);
            float hh = sigf(ao) * tanhf(cc);
            c_reg = cc;
            g_xcat2[nxt][b * 1024 + hdabs] = hh;
            g_Ahf[((size_t)t * 64 + b) * 1024 + hdabs] = __float2half(hh);
        }
        gridbar(lgen);
    }
}

// ---------------- fp16 tensor-core fc GEMM (mma.sync) ----------------
__global__ void __launch_bounds__(256, 1) hgemm_fc(const float* __restrict__ fc_b,
                                                   float* __restrict__ out) {
    extern __shared__ char sm[];
    const uint32_t sbase = smem_u32(sm);
    const int tid = threadIdx.x;
    const int wid = tid >> 5, lane = tid & 31;
    const int m0 = blockIdx.x * 128;
    const int n0 = blockIdx.y * 128;
    const int wm = wid >> 2;
    const int wn = wid & 3;

    const char* Ag = (const char*)g_Ahf + (size_t)m0 * (KD * 2);
    const char* Bg = (const char*)g_Bhf + (size_t)n0 * (KD * 2);

    float acc[4][4][4];
#pragma unroll
    for (int i = 0; i < 4; i++)
#pragma unroll
        for (int j = 0; j < 4; j++)
#pragma unroll
            for (int r = 0; r < 4; r++) acc[i][j][r] = 0.0f;

    auto load_chunk = [&](int kc, int slot) {
        uint32_t st = sbase + (uint32_t)slot * STGB;
#pragma unroll
        for (int i = 0; i < 8; i++) {
            int idx = tid + (i << 8);
            int isB = idx >> 10;
            int r = (idx & 1023) >> 3;
            int seg = idx & 7;
            uint32_t dst = st + (isB ? 16384u : 0u) + (uint32_t)(r << 7)
                         + (uint32_t)(((seg ^ (r & 7)) << 4));
            const char* src = (isB ? Bg : Ag) + (size_t)r * (KD * 2) + (size_t)kc * 128 + (seg << 4);
            cpa16(dst, src);
        }
        cpa_commit();
    };

    const int g = lane >> 3, lr = lane & 7;

    auto compute = [&](int slot) {
        uint32_t Abase = sbase + (uint32_t)slot * STGB;
        uint32_t Bbase = Abase + 16384u;
#pragma unroll
        for (int ks = 0; ks < 4; ks++) {
            uint32_t afr[4][4];
#pragma unroll
            for (int mt = 0; mt < 4; mt++) {
                int row = wm * 64 + mt * 16 + (g & 1) * 8 + lr;
                int kseg = ks * 2 + (g >> 1);
                uint32_t addr = Abase + (uint32_t)(row << 7) + (uint32_t)(((kseg ^ (row & 7)) << 4));
                LDMX4(afr[mt], addr);
            }
            uint32_t bfr[2][4];
#pragma unroll
            for (int np = 0; np < 2; np++) {
                int row = wn * 32 + np * 16 + (g >> 1) * 8 + lr;
                int kseg = ks * 2 + (g & 1);
                uint32_t addr = Bbase + (uint32_t)(row << 7) + (uint32_t)(((kseg ^ (row & 7)) << 4));
                LDMX4(bfr[np], addr);
            }
#pragma unroll
            for (int mt = 0; mt < 4; mt++)
#pragma unroll
                for (int nt = 0; nt < 4; nt++) {
                    const uint32_t* bp = &bfr[nt >> 1][(nt & 1) * 2];
                    mma16816(acc[mt][nt], afr[mt], bp[0], bp[1]);
                }
        }
    };

    load_chunk(0, 0);
    load_chunk(1, 1);
    for (int i = 0; i < NCHK; i++) {
        if (i + 1 < NCHK) cpa_wait<1>(); else cpa_wait<0>();
        __syncthreads();
        if (i + 2 < NCHK) load_chunk(i + 2, (i + 2) % 3);
        compute(i % 3);
    }

    const int quad = lane >> 2, tq = lane & 3;
#pragma unroll
    for (int mt = 0; mt < 4; mt++) {
        int mr0 = m0 + wm * 64 + mt * 16 + quad;
#pragma unroll
        for (int half = 0; half < 2; half++) {
            int m = mr0 + half * 8;
            if (m >= TD * BATCH) continue;
            int bb = m & 63, tt = m >> 6;
            float* orow = out + ((size_t)bb * TLEN + (tt + 1)) * VCAB;
#pragma unroll
            for (int nt = 0; nt < 4; nt++) {
                int n = n0 + wn * 32 + nt * 8 + tq * 2;
                float v0 = acc[mt][nt][half * 2 + 0];
                float v1 = acc[mt][nt][half * 2 + 1];
                if (n < VCAB)     orow[n]     = v0 + fc_b[n];
                if (n + 1 < VCAB) orow[n + 1] = v1 + fc_b[n + 1];
            }
        }
    }
}

// ---------------- generic tiled SGEMM: C[M,N] = A[M,K] @ B[N,K]^T + bias ----------------
__global__ void sgemm64(int M, int N, int K,
                        int asel, int lda,
                        const float* __restrict__ Bp, int ldb,
                        int csel, int ldc,
                        int bsel, const float* __restrict__ biasp) {
    const float* A = (asel == 0) ? g_encX : (asel == 1) ? g_decX : g_encout;
    float* C = (csel == 0) ? g_xprojE : (csel == 1) ? g_decxp : g_encWe;
    const float* bias = (bsel == 0) ? g_benc : (bsel == 1) ? g_bdec : biasp;

    __shared__ __align__(16) float As[16][64];
    __shared__ __align__(16) float Bs[16][64];

    const int tid = threadIdx.x;
    const int tx = tid & 15, ty = tid >> 4;
    const int m0 = blockIdx.y * 64, n0 = blockIdx.x * 64;
    const int lr = tid >> 2;
    const int lk = (tid & 3) << 2;

    float acc[4][4];
#pragma unroll
    for (int i = 0; i < 4; i++)
#pragma unroll
        for (int j = 0; j < 4; j++) acc[i][j] = 0.0f;

    const bool brow_ok = (n0 + lr) < N;
    const float* Arow = A + (size_t)(m0 + lr) * lda;
    const float* Brow = Bp + (size_t)(n0 + lr) * ldb;

    for (int k0 = 0; k0 < K; k0 += 16) {
        float4 av = *reinterpret_cast<const float4*>(Arow + k0 + lk);
        float4 bv = make_float4(0.f, 0.f, 0.f, 0.f);
        if (brow_ok) bv = *reinterpret_cast<const float4*>(Brow + k0 + lk);
        As[lk + 0][lr] = av.x; As[lk + 1][lr] = av.y; As[lk + 2][lr] = av.z; As[lk + 3][lr] = av.w;
        Bs[lk + 0][lr] = bv.x; Bs[lk + 1][lr] = bv.y; Bs[lk + 2][lr] = bv.z; Bs[lk + 3][lr] = bv.w;
        __syncthreads();
#pragma unroll
        for (int kk = 0; kk < 16; kk++) {
            float4 a = *reinterpret_cast<const float4*>(&As[kk][ty << 2]);
            float4 b = *reinterpret_cast<const float4*>(&Bs[kk][tx << 2]);
            float ar[4] = {a.x, a.y, a.z, a.w};
            float br[4] = {b.x, b.y, b.z, b.w};
#pragma unroll
            for (int i = 0; i < 4; i++)
#pragma unroll
                for (int j = 0; j < 4; j++) acc[i][j] += ar[i] * br[j];
        }
        __syncthreads();
    }

#pragma unroll
    for (int i = 0; i < 4; i++) {
        int m = m0 + (ty << 2) + i;
#pragma unroll
        for (int j = 0; j < 4; j++) {
            int n = n0 + (tx << 2) + j;
            if (n < N) C[(size_t)m * ldc + n] = acc[i][j] + bias[n];
        }
    }
}

// ---------------- host driver ----------------
extern "C" void kernel_launch(void* const* d_in, const int* in_sizes, int n_in,
                              void* d_out, int out_size) {
    const int*   src     = (const int*)  d_in[0];
    const int*   trg     = (const int*)  d_in[1];
    const float* enc_emb = (const float*)d_in[2];
    const float* enc_Wih = (const float*)d_in[3];
    const float* enc_Whh = (const float*)d_in[4];
    const float* enc_bih = (const float*)d_in[5];
    const float* enc_bhh = (const float*)d_in[6];
    const float* dec_emb = (const float*)d_in[7];
    const float* dec_Wih = (const float*)d_in[8];
    const float* dec_Whh = (const float*)d_in[9];
    const float* dec_bih = (const float*)d_in[10];
    const float* dec_bhh = (const float*)d_in[11];
    const float* attn_W  = (const float*)d_in[12];
    const float* attn_b  = (const float*)d_in[13];
    const float* v_w     = (const float*)d_in[14];
    const float* fc_W    = (const float*)d_in[15];
    const float* fc_b    = (const float*)d_in[16];
    float* out = (float*)d_out;
    (void)in_sizes; (void)n_in; (void)out_size;

    const int ENC_SMEM = (512 * 16 + 64 * 129) * 4;                     // 65792
    const int DEC_SMEM = (1024 * 16 + 512 * 4 + 64 * 129 + 512 + 512 + 128 + 128) * 4; // 111872
    cudaFuncSetAttribute(hgemm_fc, cudaFuncAttributeMaxDynamicSharedMemorySize, 3 * STGB);
    cudaFuncSetAttribute(enc_persist, cudaFuncAttributeMaxDynamicSharedMemorySize, ENC_SMEM);
    cudaFuncSetAttribute(dec_persist, cudaFuncAttributeMaxDynamicSharedMemorySize, DEC_SMEM);

    // setup
    k_bias<<<8, 256>>>(enc_bih, enc_bhh, dec_bih, dec_bhh);
    k_wpack<<<(GDIM * 1024 + 255) / 256, 256>>>(dec_Wih, dec_Whh);
    k_gather_enc<<<SLEN * BATCH, EDIM>>>(enc_emb, src);
    k_gather_dec<<<TD * BATCH, EDIM>>>(dec_emb, trg);
    k_zero_out<<<(int)(((size_t)BATCH * VCAB + 255) / 256), 256>>>(out);
    k_convB_h<<<(int)(((size_t)VCAB * KD / 4 + 255) / 256), 256>>>(fc_W);

    // batched input projections (fp32)
    sgemm64<<<dim3(GDIM / 64, (SLEN * BATCH) / 64), 256>>>(
        SLEN * BATCH, GDIM, EDIM, 0, EDIM, enc_Wih, EDIM, 0, GDIM, 0, nullptr);
    sgemm64<<<dim3(GDIM / 64, (TD * BATCH) / 64), 256>>>(
        TD * BATCH, GDIM, EDIM, 1, EDIM, dec_Wih, EDIM + HDIM, 1, GDIM, 1, nullptr);

    // persistent encoder recurrence
    enc_persist<<<NB, 256, ENC_SMEM>>>(enc_Whh);

    // encWe = enc_out @ attn_W[:, H:]^T + attn_b
    sgemm64<<<dim3(HDIM / 64, (BATCH * SLEN) / 64), 256>>>(
        BATCH * SLEN, HDIM, HDIM, 2, HDIM, attn_W + HDIM, 2 * HDIM, 2, HDIM, 2, attn_b);

    // persistent decoder recurrence (writes fp16 fc A-matrix directly)
    dec_persist<<<NB, 256, DEC_SMEM>>>(attn_W, v_w);

    // tensor-core fc GEMM
    hgemm_fc<<<dim3(MPAD / 128, NPAD / 128), 256, 3 * STGB>>>(fc_b, out);
}

// round 5
// speedup vs baseline: 1.3787x; 1.3787x over previous
#include <cuda_runtime.h>
#include <cuda_fp16.h>
#include <math.h>
#include <stdint.h>

#define VCAB 50257
#define EDIM 256
#define HDIM 512
#define BATCH 64
#define SLEN 128
#define TLEN 64
#define TD 63            // decoder steps (T-1)
#define GDIM 2048        // 4*H
#define NB 128           // persistent grid size

// fc GEMM dims (fp16 mma.sync path)
#define KD 1024
#define MPAD 4096
#define NPAD 50432
#define NCHK 16          // KD / 64
#define STGB 32768       // stage bytes: A 16KB + B 16KB

// ---------------- scratch (static device allocations; no cudaMalloc) ----------------
__device__ __align__(16) float g_benc[GDIM];
__device__ __align__(16) float g_bdec[GDIM];
__device__ __align__(16) float g_encX[SLEN * BATCH * EDIM];
__device__ __align__(16) float g_xprojE[(size_t)SLEN * BATCH * GDIM];
__device__ __align__(16) float g_decX[TD * BATCH * EDIM];
__device__ __align__(16) float g_decxp[(size_t)TD * BATCH * GDIM];
__device__ __align__(16) float g_encout[(size_t)BATCH * SLEN * HDIM];
__device__ __align__(16) float g_encWe[(size_t)BATCH * SLEN * HDIM];
__device__ __align__(16) float g_hbuf[2][BATCH * HDIM];
__device__ __align__(16) float g_c[BATCH * HDIM];
__device__ __align__(16) float g_xcat2[2][BATCH * 1024];
__device__ __align__(16) float g_Wpack[(size_t)GDIM * 1024];
__device__ __align__(16) float g_gpart[(size_t)4 * BATCH * GDIM];     // gate partials (4 split-K)
__device__ __align__(16) float g_hwp2[(size_t)16 * BATCH * HDIM];     // hWh partials (16 split-K)
// fp16 operands for the tensor-core fc GEMM (pad rows stay zero: never written)
__device__ __align__(16) __half g_Ahf[(size_t)MPAD * KD];
__device__ __align__(16) __half g_Bhf[(size_t)NPAD * KD];

// software grid barrier state
__device__ int g_bar_cnt;
__device__ volatile unsigned g_bar_gen;

__device__ __forceinline__ float sigf(float x) { return 1.0f / (1.0f + expf(-x)); }

__device__ __forceinline__ void gridbar(unsigned& lgen) {
    __syncthreads();
    if (threadIdx.x == 0) {
        __threadfence();
        unsigned target = lgen + 1;
        if (atomicAdd(&g_bar_cnt, 1) == NB - 1) {
            atomicExch(&g_bar_cnt, 0);
            __threadfence();
            atomicExch((unsigned*)&g_bar_gen, target);
        } else {
            while (g_bar_gen != target) { __nanosleep(32); }
        }
        __threadfence();
    }
    lgen++;
    __syncthreads();
}

// ---------------- PTX helpers (compute_103-safe) ----------------
__device__ __forceinline__ uint32_t smem_u32(const void* p) {
    uint32_t a;
    asm("{ .reg .u64 t; cvta.to.shared.u64 t, %1; cvt.u32.u64 %0, t; }" : "=r"(a) : "l"(p));
    return a;
}
__device__ __forceinline__ void cpa16(uint32_t dst, const void* src) {
    asm volatile("cp.async.cg.shared.global [%0], [%1], 16;" :: "r"(dst), "l"(src) : "memory");
}
__device__ __forceinline__ void cpa_commit() { asm volatile("cp.async.commit_group;" ::: "memory"); }
template <int N> __device__ __forceinline__ void cpa_wait() {
    asm volatile("cp.async.wait_group %0;" :: "n"(N) : "memory");
}
#define LDMX4(r, addr) \
    asm volatile("ldmatrix.sync.aligned.m8n8.x4.shared.b16 {%0,%1,%2,%3}, [%4];" \
        : "=r"((r)[0]), "=r"((r)[1]), "=r"((r)[2]), "=r"((r)[3]) : "r"(addr))
__device__ __forceinline__ void mma16816(float* c, const uint32_t* a, uint32_t b0, uint32_t b1) {
    asm volatile("mma.sync.aligned.m16n8k16.row.col.f32.f16.f16.f32 "
        "{%0,%1,%2,%3}, {%4,%5,%6,%7}, {%8,%9}, {%0,%1,%2,%3};"
        : "+f"(c[0]), "+f"(c[1]), "+f"(c[2]), "+f"(c[3])
        : "r"(a[0]), "r"(a[1]), "r"(a[2]), "r"(a[3]), "r"(b0), "r"(b1));
}

// ---------------- setup kernels ----------------
__global__ void k_bias(const float* __restrict__ ebih, const float* __restrict__ ebhh,
                       const float* __restrict__ dbih, const float* __restrict__ dbhh) {
    int j = blockIdx.x * blockDim.x + threadIdx.x;
    if (j < GDIM) {
        g_benc[j] = ebih[j] + ebhh[j];
        g_bdec[j] = dbih[j] + dbhh[j];
    }
}

__global__ void k_wpack(const float* __restrict__ dWih, const float* __restrict__ dWhh) {
    size_t idx = (size_t)blockIdx.x * blockDim.x + threadIdx.x;
    if (idx >= (size_t)GDIM * 1024) return;
    int j = (int)(idx >> 10);
    int k = (int)(idx & 1023);
    g_Wpack[idx] = (k < HDIM) ? dWhh[(size_t)j * HDIM + k]
                              : dWih[(size_t)j * (EDIM + HDIM) + EDIM + (k - HDIM)];
}

__global__ void k_gather_enc(const float* __restrict__ emb, const int* __restrict__ src) {
    int m = blockIdx.x;
    int e = threadIdx.x;
    int s = m >> 6, b = m & 63;
    int tok = src[b * SLEN + s];
    g_encX[(size_t)m * EDIM + e] = emb[(size_t)tok * EDIM + e];
}

__global__ void k_gather_dec(const float* __restrict__ emb, const int* __restrict__ trg) {
    int m = blockIdx.x;
    int e = threadIdx.x;
    int t = m >> 6, b = m & 63;
    int tok = trg[b * TLEN + t];
    g_decX[(size_t)m * EDIM + e] = emb[(size_t)tok * EDIM + e];
}

__global__ void k_zero_out(float* __restrict__ out) {
    size_t idx = (size_t)blockIdx.x * blockDim.x + threadIdx.x;
    if (idx >= (size_t)BATCH * VCAB) return;
    size_t b = idx / VCAB, v = idx % VCAB;
    out[b * (size_t)TLEN * VCAB + v] = 0.0f;
}

__global__ void k_convB_h(const float* __restrict__ W) {
    size_t i4 = (size_t)blockIdx.x * blockDim.x + threadIdx.x;
    if (i4 * 4 >= (size_t)VCAB * KD) return;
    float4 v = *reinterpret_cast<const float4*>(W + i4 * 4);
    __half2* dst = reinterpret_cast<__half2*>(g_Bhf + i4 * 4);
    dst[0] = __floats2half2_rn(v.x, v.y);
    dst[1] = __floats2half2_rn(v.z, v.w);
}

// ---------------- persistent encoder: sgemm_sk-style tiles + fused LSTM ----------------
// 128 blocks = 32 n-tiles x 4 split-K. Weights cached in smem once.
__global__ void __launch_bounds__(256, 1) enc_persist2(const float* __restrict__ Whh) {
    __shared__ __align__(16) float Bs_s[128 * 64];   // [k 0..127][n 0..63] 32KB
    __shared__ __align__(16) float As_s[16 * 64];    // chunk buffer

    const int tid = threadIdx.x, bid = blockIdx.x;
    const int nt = bid & 31, kz = bid >> 5;
    const int n0 = nt * 64, k0s = kz * 128;
    const int tx = tid & 15, ty = tid >> 4;
    const int lr = tid >> 2, lk = (tid & 3) << 2;
    const int idxl = bid * 256 + tid;                 // 0..32767
    const int b_l = idxl >> 9, j_l = idxl & 511;      // LSTM ownership
    unsigned lgen = g_bar_gen;

    // cache this block's Whh tile: Bs_s[k*64+n] = Whh[(n0+n)*512 + k0s + k]
    for (int i = tid; i < 8192; i += 256) {
        int k = i >> 6, n = i & 63;
        Bs_s[i] = Whh[(size_t)(n0 + n) * 512 + k0s + k];
    }
    g_hbuf[0][idxl] = 0.0f;
    float c_reg = 0.0f;
    gridbar(lgen);

    for (int t = 0; t < SLEN; t++) {
        const float* hcur = g_hbuf[t & 1];
        float acc[4][4];
#pragma unroll
        for (int i = 0; i < 4; i++)
#pragma unroll
            for (int j = 0; j < 4; j++) acc[i][j] = 0.0f;

        for (int c = 0; c < 8; c++) {
            float4 av = *reinterpret_cast<const float4*>(hcur + lr * 512 + k0s + c * 16 + lk);
            __syncthreads();
            As_s[(lk + 0) * 64 + lr] = av.x;
            As_s[(lk + 1) * 64 + lr] = av.y;
            As_s[(lk + 2) * 64 + lr] = av.z;
            As_s[(lk + 3) * 64 + lr] = av.w;
            __syncthreads();
#pragma unroll
            for (int kk = 0; kk < 16; kk++) {
                float4 a = *reinterpret_cast<const float4*>(&As_s[kk * 64 + (ty << 2)]);
                float4 w = *reinterpret_cast<const float4*>(&Bs_s[(c * 16 + kk) * 64 + (tx << 2)]);
                float ar[4] = {a.x, a.y, a.z, a.w};
                float wr[4] = {w.x, w.y, w.z, w.w};
#pragma unroll
                for (int i = 0; i < 4; i++)
#pragma unroll
                    for (int j = 0; j < 4; j++) acc[i][j] += ar[i] * wr[j];
            }
        }
#pragma unroll
        for (int i = 0; i < 4; i++) {
            int m = (ty << 2) + i;
            float4 v = make_float4(acc[i][0], acc[i][1], acc[i][2], acc[i][3]);
            *reinterpret_cast<float4*>(&g_gpart[((size_t)kz * 64 + m) * GDIM + n0 + (tx << 2)]) = v;
        }
        gridbar(lgen);

        // fused reduce + LSTM (thread owns (b_l, j_l); c in register)
        {
            size_t xb = ((size_t)t * 64 + b_l) * GDIM;
            float gi = g_xprojE[xb + j_l];
            float gf = g_xprojE[xb + 512 + j_l];
            float gg = g_xprojE[xb + 1024 + j_l];
            float go = g_xprojE[xb + 1536 + j_l];
#pragma unroll
            for (int s2 = 0; s2 < 4; s2++) {
                const float* p = g_gpart + ((size_t)s2 * 64 + b_l) * GDIM;
                gi += p[j_l]; gf += p[512 + j_l]; gg += p[1024 + j_l]; go += p[1536 + j_l];
            }
            float cc = sigf(gf) * c_reg + sigf(gi) * tanhf(gg);
            float hh = sigf(go) * tanhf(cc);
            c_reg = cc;
            g_encout[((size_t)b_l * SLEN + t) * 512 + j_l] = hh;
            g_hbuf[(t + 1) & 1][b_l * 512 + j_l] = hh;
        }
        gridbar(lgen);
    }
    g_c[b_l * 512 + j_l] = c_reg;
}

// ---------------- persistent decoder: 4 phases/step, weights cached in smem ----------------
__global__ void __launch_bounds__(256, 1) dec_persist2(const float* __restrict__ attnW,
                                                       const float* __restrict__ vw) {
    extern __shared__ float sd[];
    float* WC = sd;                  // [256k][64n] gates weights      64KB
    float* WA = WC + 16384;          // [32k][64n]  hWh weights         8KB
    float* As_s = WA + 2048;         // [16][64]                        4KB
    float* vws = As_s + 1024;        // 512
    float* hwhs = vws + 512;         // 512
    float* sc = hwhs + 512;          // 128
    float* red = sc + 128;           // 128

    const int tid = threadIdx.x, bid = blockIdx.x;
    const int tx = tid & 15, ty = tid >> 4;
    const int lr = tid >> 2, lk = (tid & 3) << 2;
    const int idxl = bid * 256 + tid;
    const int b_l = idxl >> 9, j_l = idxl & 511;
    // phase A decomposition: 8 n-tiles (512) x 16 split-K (k-slice 32)
    const int ntA = bid & 7, kzA = bid >> 3;
    const int n0A = ntA * 64, k0A = kzA * 32;
    // phase C decomposition: 32 n-tiles (2048) x 4 split-K (k-slice 256)
    const int ntC = bid & 31, kzC = bid >> 5;
    const int n0C = ntC * 64, k0C = kzC * 256;
    unsigned lgen = g_bar_gen;

    // cache weights
    for (int i = tid; i < 16384; i += 256) {
        int k = i >> 6, n = i & 63;
        WC[i] = g_Wpack[(size_t)(n0C + n) * 1024 + k0C + k];
    }
    for (int i = tid; i < 2048; i += 256) {
        int k = i >> 6, n = i & 63;
        WA[i] = attnW[(size_t)(n0A + n) * 1024 + k0A + k];
    }
    if (bid < 64)
        for (int i = tid; i < 512; i += 256) vws[i] = vw[i];

    // init: xcat[0] h-part = encoder final h (g_hbuf[0]); c from encoder
    g_xcat2[0][b_l * 1024 + j_l] = g_hbuf[0][b_l * 512 + j_l];
    float c_reg = g_c[b_l * 512 + j_l];
    gridbar(lgen);

    for (int t = 0; t < TD; t++) {
        const int cur = t & 1, nxt = cur ^ 1;
        const float* xc = g_xcat2[cur];

        // ---- Phase A: hWh partials [64m x 64n x 32k] ----
        {
            float acc[4][4];
#pragma unroll
            for (int i = 0; i < 4; i++)
#pragma unroll
                for (int j = 0; j < 4; j++) acc[i][j] = 0.0f;
            for (int c = 0; c < 2; c++) {
                float4 av = *reinterpret_cast<const float4*>(xc + lr * 1024 + k0A + c * 16 + lk);
                __syncthreads();
                As_s[(lk + 0) * 64 + lr] = av.x;
                As_s[(lk + 1) * 64 + lr] = av.y;
                As_s[(lk + 2) * 64 + lr] = av.z;
                As_s[(lk + 3) * 64 + lr] = av.w;
                __syncthreads();
#pragma unroll
                for (int kk = 0; kk < 16; kk++) {
                    float4 a = *reinterpret_cast<const float4*>(&As_s[kk * 64 + (ty << 2)]);
                    float4 w = *reinterpret_cast<const float4*>(&WA[(c * 16 + kk) * 64 + (tx << 2)]);
                    float ar[4] = {a.x, a.y, a.z, a.w};
                    float wr[4] = {w.x, w.y, w.z, w.w};
#pragma unroll
                    for (int i = 0; i < 4; i++)
#pragma unroll
                        for (int j = 0; j < 4; j++) acc[i][j] += ar[i] * wr[j];
                }
            }
#pragma unroll
            for (int i = 0; i < 4; i++) {
                int m = (ty << 2) + i;
                float4 v = make_float4(acc[i][0], acc[i][1], acc[i][2], acc[i][3]);
                *reinterpret_cast<float4*>(&g_hwp2[((size_t)kzA * 64 + m) * 512 + n0A + (tx << 2)]) = v;
            }
        }
        gridbar(lgen);

        // ---- Phase B: attention (blocks 0..63; b = bid) ----
        if (bid < 64) {
            const int bb = bid;
            for (int i = tid; i < 512; i += 256) {
                float s = 0.0f;
#pragma unroll
                for (int kz = 0; kz < 16; kz++) s += g_hwp2[((size_t)kz * 64 + bb) * 512 + i];
                hwhs[i] = s;
            }
            __syncthreads();
            int warp = tid >> 5, lane = tid & 31;
            for (int s = warp; s < SLEN; s += 8) {
                const float* we = &g_encWe[((size_t)bb * SLEN + s) * 512];
                float a = 0.0f;
                for (int j = lane; j < 512; j += 32)
                    a += tanhf(hwhs[j] + we[j]) * vws[j];
#pragma unroll
                for (int o = 16; o > 0; o >>= 1) a += __shfl_xor_sync(0xffffffffu, a, o);
                if (lane == 0) sc[s] = a;
            }
            __syncthreads();
            if (tid < SLEN) red[tid] = sc[tid];
            __syncthreads();
            for (int o = 64; o > 0; o >>= 1) {
                if (tid < o) red[tid] = fmaxf(red[tid], red[tid + o]);
                __syncthreads();
            }
            float mx = red[0];
            __syncthreads();
            float e = 0.0f;
            if (tid < SLEN) { e = expf(sc[tid] - mx); red[tid] = e; }
            __syncthreads();
            for (int o = 64; o > 0; o >>= 1) {
                if (tid < o) red[tid] += red[tid + o];
                __syncthreads();
            }
            float inv = 1.0f / red[0];
            __syncthreads();
            if (tid < SLEN) sc[tid] = e * inv;
            __syncthreads();
            float c0 = 0.0f, c1 = 0.0f;
            const float* eo = &g_encout[(size_t)bb * SLEN * 512];
            for (int s = 0; s < SLEN; s++) {
                float w = sc[s];
                c0 += w * eo[s * 512 + tid];
                c1 += w * eo[s * 512 + tid + 256];
            }
            g_xcat2[cur][bb * 1024 + 512 + tid] = c0;
            g_xcat2[cur][bb * 1024 + 512 + tid + 256] = c1;
            size_t ma = ((size_t)t * 64 + bb) * 1024;
            g_Ahf[ma + 512 + tid] = __float2half(c0);
            g_Ahf[ma + 512 + tid + 256] = __float2half(c1);
        }
        gridbar(lgen);

        // ---- Phase C: gate partials [64m x 64n x 256k] ----
        {
            float acc[4][4];
#pragma unroll
            for (int i = 0; i < 4; i++)
#pragma unroll
                for (int j = 0; j < 4; j++) acc[i][j] = 0.0f;
            for (int c = 0; c < 16; c++) {
                float4 av = *reinterpret_cast<const float4*>(xc + lr * 1024 + k0C + c * 16 + lk);
                __syncthreads();
                As_s[(lk + 0) * 64 + lr] = av.x;
                As_s[(lk + 1) * 64 + lr] = av.y;
                As_s[(lk + 2) * 64 + lr] = av.z;
                As_s[(lk + 3) * 64 + lr] = av.w;
                __syncthreads();
#pragma unroll
                for (int kk = 0; kk < 16; kk++) {
                    float4 a = *reinterpret_cast<const float4*>(&As_s[kk * 64 + (ty << 2)]);
                    float4 w = *reinterpret_cast<const float4*>(&WC[(c * 16 + kk) * 64 + (tx << 2)]);
                    float ar[4] = {a.x, a.y, a.z, a.w};
                    float wr[4] = {w.x, w.y, w.z, w.w};
#pragma unroll
                    for (int i = 0; i < 4; i++)
#pragma unroll
                        for (int j = 0; j < 4; j++) acc[i][j] += ar[i] * wr[j];
                }
            }
#pragma unroll
            for (int i = 0; i < 4; i++) {
                int m = (ty << 2) + i;
                float4 v = make_float4(acc[i][0], acc[i][1], acc[i][2], acc[i][3]);
                *reinterpret_cast<float4*>(&g_gpart[((size_t)kzC * 64 + m) * GDIM + n0C + (tx << 2)]) = v;
            }
        }
        gridbar(lgen);

        // ---- Phase D: reduce + LSTM + fp16 A write ----
        {
            size_t xb = ((size_t)t * 64 + b_l) * GDIM;
            float gi = g_decxp[xb + j_l];
            float gf = g_decxp[xb + 512 + j_l];
            float gg = g_decxp[xb + 1024 + j_l];
            float go = g_decxp[xb + 1536 + j_l];
#pragma unroll
            for (int s2 = 0; s2 < 4; s2++) {
                const float* p = g_gpart + ((size_t)s2 * 64 + b_l) * GDIM;
                gi += p[j_l]; gf += p[512 + j_l]; gg += p[1024 + j_l]; go += p[1536 + j_l];
            }
            float cc = sigf(gf) * c_reg + sigf(gi) * tanhf(gg);
            float hh = sigf(go) * tanhf(cc);
            c_reg = cc;
            g_xcat2[nxt][b_l * 1024 + j_l] = hh;
            g_Ahf[((size_t)t * 64 + b_l) * 1024 + j_l] = __float2half(hh);
        }
        gridbar(lgen);
    }
}

// ---------------- fp16 tensor-core fc GEMM (mma.sync) ----------------
__global__ void __launch_bounds__(256, 1) hgemm_fc(const float* __restrict__ fc_b,
                                                   float* __restrict__ out) {
    extern __shared__ char smc[];
    const uint32_t sbase = smem_u32(smc);
    const int tid = threadIdx.x;
    const int wid = tid >> 5, lane = tid & 31;
    const int m0 = blockIdx.x * 128;
    const int n0 = blockIdx.y * 128;
    const int wm = wid >> 2;
    const int wn = wid & 3;

    const char* Ag = (const char*)g_Ahf + (size_t)m0 * (KD * 2);
    const char* Bg = (const char*)g_Bhf + (size_t)n0 * (KD * 2);

    float acc[4][4][4];
#pragma unroll
    for (int i = 0; i < 4; i++)
#pragma unroll
        for (int j = 0; j < 4; j++)
#pragma unroll
            for (int r = 0; r < 4; r++) acc[i][j][r] = 0.0f;

    auto load_chunk = [&](int kc, int slot) {
        uint32_t st = sbase + (uint32_t)slot * STGB;
#pragma unroll
        for (int i = 0; i < 8; i++) {
            int idx = tid + (i << 8);
            int isB = idx >> 10;
            int r = (idx & 1023) >> 3;
            int seg = idx & 7;
            uint32_t dst = st + (isB ? 16384u : 0u) + (uint32_t)(r << 7)
                         + (uint32_t)(((seg ^ (r & 7)) << 4));
            const char* src = (isB ? Bg : Ag) + (size_t)r * (KD * 2) + (size_t)kc * 128 + (seg << 4);
            cpa16(dst, src);
        }
        cpa_commit();
    };

    const int g = lane >> 3, lr = lane & 7;

    auto compute = [&](int slot) {
        uint32_t Abase = sbase + (uint32_t)slot * STGB;
        uint32_t Bbase = Abase + 16384u;
#pragma unroll
        for (int ks = 0; ks < 4; ks++) {
            uint32_t afr[4][4];
#pragma unroll
            for (int mt = 0; mt < 4; mt++) {
                int row = wm * 64 + mt * 16 + (g & 1) * 8 + lr;
                int kseg = ks * 2 + (g >> 1);
                uint32_t addr = Abase + (uint32_t)(row << 7) + (uint32_t)(((kseg ^ (row & 7)) << 4));
                LDMX4(afr[mt], addr);
            }
            uint32_t bfr[2][4];
#pragma unroll
            for (int np = 0; np < 2; np++) {
                int row = wn * 32 + np * 16 + (g >> 1) * 8 + lr;
                int kseg = ks * 2 + (g & 1);
                uint32_t addr = Bbase + (uint32_t)(row << 7) + (uint32_t)(((kseg ^ (row & 7)) << 4));
                LDMX4(bfr[np], addr);
            }
#pragma unroll
            for (int mt = 0; mt < 4; mt++)
#pragma unroll
                for (int nt = 0; nt < 4; nt++) {
                    const uint32_t* bp = &bfr[nt >> 1][(nt & 1) * 2];
                    mma16816(acc[mt][nt], afr[mt], bp[0], bp[1]);
                }
        }
    };

    load_chunk(0, 0);
    load_chunk(1, 1);
    for (int i = 0; i < NCHK; i++) {
        if (i + 1 < NCHK) cpa_wait<1>(); else cpa_wait<0>();
        __syncthreads();
        if (i + 2 < NCHK) load_chunk(i + 2, (i + 2) % 3);
        compute(i % 3);
    }

    const int quad = lane >> 2, tq = lane & 3;
#pragma unroll
    for (int mt = 0; mt < 4; mt++) {
        int mr0 = m0 + wm * 64 + mt * 16 + quad;
#pragma unroll
        for (int half = 0; half < 2; half++) {
            int m = mr0 + half * 8;
            if (m >= TD * BATCH) continue;
            int bb = m & 63, tt = m >> 6;
            float* orow = out + ((size_t)bb * TLEN + (tt + 1)) * VCAB;
#pragma unroll
            for (int nt = 0; nt < 4; nt++) {
                int n = n0 + wn * 32 + nt * 8 + tq * 2;
                float v0 = acc[mt][nt][half * 2 + 0];
                float v1 = acc[mt][nt][half * 2 + 1];
                if (n < VCAB)     orow[n]     = v0 + fc_b[n];
                if (n + 1 < VCAB) orow[n + 1] = v1 + fc_b[n + 1];
            }
        }
    }
}

// ---------------- generic tiled SGEMM: C[M,N] = A[M,K] @ B[N,K]^T + bias ----------------
__global__ void sgemm64(int M, int N, int K,
                        int asel, int lda,
                        const float* __restrict__ Bp, int ldb,
                        int csel, int ldc,
                        int bsel, const float* __restrict__ biasp) {
    const float* A = (asel == 0) ? g_encX : (asel == 1) ? g_decX : g_encout;
    float* C = (csel == 0) ? g_xprojE : (csel == 1) ? g_decxp : g_encWe;
    const float* bias = (bsel == 0) ? g_benc : (bsel == 1) ? g_bdec : biasp;

    __shared__ __align__(16) float As[16][64];
    __shared__ __align__(16) float Bs[16][64];

    const int tid = threadIdx.x;
    const int tx = tid & 15, ty = tid >> 4;
    const int m0 = blockIdx.y * 64, n0 = blockIdx.x * 64;
    const int lr = tid >> 2;
    const int lk = (tid & 3) << 2;

    float acc[4][4];
#pragma unroll
    for (int i = 0; i < 4; i++)
#pragma unroll
        for (int j = 0; j < 4; j++) acc[i][j] = 0.0f;

    const bool brow_ok = (n0 + lr) < N;
    const float* Arow = A + (size_t)(m0 + lr) * lda;
    const float* Brow = Bp + (size_t)(n0 + lr) * ldb;

    for (int k0 = 0; k0 < K; k0 += 16) {
        float4 av = *reinterpret_cast<const float4*>(Arow + k0 + lk);
        float4 bv = make_float4(0.f, 0.f, 0.f, 0.f);
        if (brow_ok) bv = *reinterpret_cast<const float4*>(Brow + k0 + lk);
        As[lk + 0][lr] = av.x; As[lk + 1][lr] = av.y; As[lk + 2][lr] = av.z; As[lk + 3][lr] = av.w;
        Bs[lk + 0][lr] = bv.x; Bs[lk + 1][lr] = bv.y; Bs[lk + 2][lr] = bv.z; Bs[lk + 3][lr] = bv.w;
        __syncthreads();
#pragma unroll
        for (int kk = 0; kk < 16; kk++) {
            float4 a = *reinterpret_cast<const float4*>(&As[kk][ty << 2]);
            float4 b = *reinterpret_cast<const float4*>(&Bs[kk][tx << 2]);
            float ar[4] = {a.x, a.y, a.z, a.w};
            float br[4] = {b.x, b.y, b.z, b.w};
#pragma unroll
            for (int i = 0; i < 4; i++)
#pragma unroll
                for (int j = 0; j < 4; j++) acc[i][j] += ar[i] * br[j];
        }
        __syncthreads();
    }

#pragma unroll
    for (int i = 0; i < 4; i++) {
        int m = m0 + (ty << 2) + i;
#pragma unroll
        for (int j = 0; j < 4; j++) {
            int n = n0 + (tx << 2) + j;
            if (n < N) C[(size_t)m * ldc + n] = acc[i][j] + bias[n];
        }
    }
}

// ---------------- host driver ----------------
extern "C" void kernel_launch(void* const* d_in, const int* in_sizes, int n_in,
                              void* d_out, int out_size) {
    const int*   src     = (const int*)  d_in[0];
    const int*   trg     = (const int*)  d_in[1];
    const float* enc_emb = (const float*)d_in[2];
    const float* enc_Wih = (const float*)d_in[3];
    const float* enc_Whh = (const float*)d_in[4];
    const float* enc_bih = (const float*)d_in[5];
    const float* enc_bhh = (const float*)d_in[6];
    const float* dec_emb = (const float*)d_in[7];
    const float* dec_Wih = (const float*)d_in[8];
    const float* dec_Whh = (const float*)d_in[9];
    const float* dec_bih = (const float*)d_in[10];
    const float* dec_bhh = (const float*)d_in[11];
    const float* attn_W  = (const float*)d_in[12];
    const float* attn_b  = (const float*)d_in[13];
    const float* v_w     = (const float*)d_in[14];
    const float* fc_W    = (const float*)d_in[15];
    const float* fc_b    = (const float*)d_in[16];
    float* out = (float*)d_out;
    (void)in_sizes; (void)n_in; (void)out_size;

    const int DEC_SMEM = (16384 + 2048 + 1024 + 512 + 512 + 128 + 128) * 4;  // 82944
    cudaFuncSetAttribute(hgemm_fc, cudaFuncAttributeMaxDynamicSharedMemorySize, 3 * STGB);
    cudaFuncSetAttribute(dec_persist2, cudaFuncAttributeMaxDynamicSharedMemorySize, DEC_SMEM);

    // setup
    k_bias<<<8, 256>>>(enc_bih, enc_bhh, dec_bih, dec_bhh);
    k_wpack<<<(GDIM * 1024 + 255) / 256, 256>>>(dec_Wih, dec_Whh);
    k_gather_enc<<<SLEN * BATCH, EDIM>>>(enc_emb, src);
    k_gather_dec<<<TD * BATCH, EDIM>>>(dec_emb, trg);
    k_zero_out<<<(int)(((size_t)BATCH * VCAB + 255) / 256), 256>>>(out);
    k_convB_h<<<(int)(((size_t)VCAB * KD / 4 + 255) / 256), 256>>>(fc_W);

    // batched input projections (fp32)
    sgemm64<<<dim3(GDIM / 64, (SLEN * BATCH) / 64), 256>>>(
        SLEN * BATCH, GDIM, EDIM, 0, EDIM, enc_Wih, EDIM, 0, GDIM, 0, nullptr);
    sgemm64<<<dim3(GDIM / 64, (TD * BATCH) / 64), 256>>>(
        TD * BATCH, GDIM, EDIM, 1, EDIM, dec_Wih, EDIM + HDIM, 1, GDIM, 1, nullptr);

    // persistent encoder recurrence (sgemm_sk-style tiles + fused LSTM)
    enc_persist2<<<NB, 256>>>(enc_Whh);

    // encWe = enc_out @ attn_W[:, H:]^T + attn_b
    sgemm64<<<dim3(HDIM / 64, (BATCH * SLEN) / 64), 256>>>(
        BATCH * SLEN, HDIM, HDIM, 2, HDIM, attn_W + HDIM, 2 * HDIM, 2, HDIM, 2, attn_b);

    // persistent decoder recurrence (writes fp16 fc A-matrix directly)
    dec_persist2<<<NB, 256, DEC_SMEM>>>(attn_W, v_w);

    // tensor-core fc GEMM
    hgemm_fc<<<dim3(MPAD / 128, NPAD / 128), 256, 3 * STGB>>>(fc_b, out);
}